// round 3
// baseline (speedup 1.0000x reference)
#include <cuda_runtime.h>
#include <cuda_bf16.h>
#include <math.h>

// ContrastLoss: feat [4,64,512,512] f32, gt [4,19,512,512] i32 -> scalar f32

#define NPIX  (4 * 262144)
#define HW    262144
#define KCLS  19
#define CCH   64
#define TAUF  0.07f
#define LOG2E 1.4426950408889634f

// -------- device scratch --------
__device__ float          g_k0[KCLS * CCH];
__device__ float          g_k0n[KCLS * CCH];
__device__ unsigned       g_maskbuf[NPIX];
__device__ int            g_numpos;
__device__ double         g_loss;

// -------- f32x2 helpers --------
__device__ __forceinline__ unsigned long long pack2(float a, float b) {
    unsigned long long r;
    asm("mov.b64 %0, {%1, %2};" : "=l"(r) : "f"(a), "f"(b));
    return r;
}
__device__ __forceinline__ void unpack2(unsigned long long v, float& a, float& b) {
    asm("mov.b64 {%0, %1}, %2;" : "=f"(a), "=f"(b) : "l"(v));
}
__device__ __forceinline__ void ffma2(unsigned long long& d, unsigned long long a,
                                      unsigned long long b) {
    asm("fma.rn.f32x2 %0, %1, %2, %0;" : "+l"(d) : "l"(a), "l"(b));
}

// -------- kernel 0: zero accumulators --------
__global__ void k_zero() {
    int t = blockIdx.x * 256 + threadIdx.x;
    if (t < KCLS * CCH) g_k0[t] = 0.f;
    if (t == 0) { g_numpos = 0; g_loss = 0.0; }
}

// -------- kernel 1: prototype scatter-sum (mask-as-float FFMA2) --------
// Tile = 512 px. Block 256: thread j -> channel c=j>>2, quarter q=j&3.
// Shared float2 masks laid out [k][pair] so build STS is coalesced and the
// accumulate LDS.128 (pairs pr,pr+1 for class k) is warp-broadcast (4 addrs).
__global__ __launch_bounds__(256, 2) void k_proto(const float* __restrict__ feat,
                                                  const int* __restrict__ gt) {
    __shared__ unsigned long long smf[KCLS * 256];   // 38 KB: [k][pair] (1,0 floats packed)
    const int j = threadIdx.x;
    const int c = j >> 2;
    const int q = j & 3;

    unsigned long long acc[KCLS];
#pragma unroll
    for (int k = 0; k < KCLS; k++) acc[k] = 0ull;
    int cnt = 0;

    for (int tile = blockIdx.x * 512; tile < NPIX; tile += gridDim.x * 512) {
        const int b  = tile >> 18;
        const int hw = tile & (HW - 1);

        // --- build: thread j owns pair j (pixels tile+2j, tile+2j+1) ---
        {
            const int p = hw + 2 * j;
            unsigned b0 = 0, b1 = 0;
#pragma unroll
            for (int k = 0; k < KCLS; k++) {
                const int2 g = *reinterpret_cast<const int2*>(
                    gt + (size_t)(b * KCLS + k) * HW + p);
                const unsigned e0 = (g.x == 1), e1 = (g.y == 1);
                b0 |= e0 << k;
                b1 |= e1 << k;
                smf[k * 256 + j] = pack2(e0 ? 1.f : 0.f, e1 ? 1.f : 0.f);
            }
            *reinterpret_cast<uint2*>(&g_maskbuf[tile + 2 * j]) = make_uint2(b0, b1);
            cnt += __popc(b0) + __popc(b1);
        }
        __syncthreads();

        // --- accumulate: channel c, pixels q*4 + 16t .. +3 (t = 0..31) ---
        const float* fb = feat + (size_t)(b * CCH + c) * HW + hw;
#pragma unroll 2
        for (int t = 0; t < 32; t++) {
            const int px = q * 4 + t * 16;
            const float4 f = *reinterpret_cast<const float4*>(fb + px);
            const unsigned long long f2a = pack2(f.x, f.y);
            const unsigned long long f2b = pack2(f.z, f.w);
            const int pr = px >> 1;                    // even
#pragma unroll
            for (int k = 0; k < KCLS; k++) {
                const ulonglong2 m = *reinterpret_cast<const ulonglong2*>(&smf[k * 256 + pr]);
                ffma2(acc[k], f2a, m.x);
                ffma2(acc[k], f2b, m.y);
            }
        }
        __syncthreads();
    }

    // reduce q-subgroup (lanes differing in low 2 bits) via shuffle, then atomic
#pragma unroll
    for (int k = 0; k < KCLS; k++) {
        float a, bq;
        unpack2(acc[k], a, bq);
        float v = a + bq;
        v += __shfl_xor_sync(0xffffffffu, v, 1);
        v += __shfl_xor_sync(0xffffffffu, v, 2);
        if (q == 0) atomicAdd(&g_k0[k * CCH + c], v);
    }
#pragma unroll
    for (int o = 16; o; o >>= 1) cnt += __shfl_xor_sync(0xffffffffu, cnt, o);
    if ((j & 31) == 0) atomicAdd(&g_numpos, cnt);
}

// -------- kernel 2: normalize prototypes --------
__global__ void k_norm() {
    const int k    = threadIdx.x >> 5;
    const int lane = threadIdx.x & 31;
    if (k >= KCLS) return;
    const float v0 = g_k0[k * CCH + lane];
    const float v1 = g_k0[k * CCH + 32 + lane];
    float s = v0 * v0 + v1 * v1;
#pragma unroll
    for (int o = 16; o; o >>= 1) s += __shfl_xor_sync(0xffffffffu, s, o);
    const float inv = 1.f / fmaxf(sqrtf(s), 1e-12f);
    g_k0n[k * CCH + lane]      = v0 * inv;
    g_k0n[k * CCH + 32 + lane] = v1 * inv;
}

// -------- per-pixel softmax/NLL epilogue --------
__device__ __forceinline__ float pix_loss(const float* __restrict__ l,
                                          float ssum, unsigned m) {
    const float sc = 1.f / (fmaxf(sqrtf(ssum), 1e-12f) * TAUF);
    float v[KCLS];
    float mx = -1e30f;
#pragma unroll
    for (int k = 0; k < KCLS; k++) {
        v[k] = l[k] * sc;
        mx = fmaxf(mx, v[k]);
    }
    float se = 0.f, sl = 0.f;
#pragma unroll
    for (int k = 0; k < KCLS; k++) {
        se += exp2f((v[k] - mx) * LOG2E);
        if (m & (1u << k)) sl += v[k];
    }
    return (float)__popc(m) * (mx + logf(se)) - sl;
}

// -------- kernel 3: logits + log-softmax NLL, pixel-pair f32x2 --------
// Thread owns 4 consecutive pixels. Prototypes pre-duplicated (kn,kn) in shared;
// LDS.128 (warp-uniform -> broadcast) serves 2 channels x 4 pixels.
__global__ __launch_bounds__(256, 2) void k_loss(const float* __restrict__ feat) {
    __shared__ unsigned long long sknd[KCLS * CCH];     // 9.5 KB
    for (int t = threadIdx.x; t < KCLS * CCH; t += 256) {
        const float v = g_k0n[t];
        sknd[t] = pack2(v, v);
    }
    __syncthreads();

    float lsum = 0.f;
    for (int p4 = (blockIdx.x * 256 + threadIdx.x) * 4; p4 < NPIX;
         p4 += gridDim.x * 256 * 4) {
        const uint4 m  = *reinterpret_cast<const uint4*>(&g_maskbuf[p4]);
        const int   b  = p4 >> 18;
        const int   hw = p4 & (HW - 1);
        const float* fb = feat + (size_t)(b * CCH) * HW + hw;

        unsigned long long acca[KCLS], accb[KCLS];
#pragma unroll
        for (int k = 0; k < KCLS; k++) { acca[k] = 0ull; accb[k] = 0ull; }
        unsigned long long ssa = 0ull, ssb = 0ull;

#pragma unroll 2
        for (int c4 = 0; c4 < 16; c4++) {
            const float4 f0 = *reinterpret_cast<const float4*>(fb + (size_t)(4 * c4 + 0) * HW);
            const float4 f1 = *reinterpret_cast<const float4*>(fb + (size_t)(4 * c4 + 1) * HW);
            const float4 f2 = *reinterpret_cast<const float4*>(fb + (size_t)(4 * c4 + 2) * HW);
            const float4 f3 = *reinterpret_cast<const float4*>(fb + (size_t)(4 * c4 + 3) * HW);
            const unsigned long long A0 = pack2(f0.x, f0.y), B0 = pack2(f0.z, f0.w);
            const unsigned long long A1 = pack2(f1.x, f1.y), B1 = pack2(f1.z, f1.w);
            const unsigned long long A2 = pack2(f2.x, f2.y), B2 = pack2(f2.z, f2.w);
            const unsigned long long A3 = pack2(f3.x, f3.y), B3 = pack2(f3.z, f3.w);
            ffma2(ssa, A0, A0); ffma2(ssb, B0, B0);
            ffma2(ssa, A1, A1); ffma2(ssb, B1, B1);
            ffma2(ssa, A2, A2); ffma2(ssb, B2, B2);
            ffma2(ssa, A3, A3); ffma2(ssb, B3, B3);
#pragma unroll
            for (int k = 0; k < KCLS; k++) {
                const ulonglong2 k01 =
                    *reinterpret_cast<const ulonglong2*>(&sknd[k * CCH + 4 * c4]);
                const ulonglong2 k23 =
                    *reinterpret_cast<const ulonglong2*>(&sknd[k * CCH + 4 * c4 + 2]);
                ffma2(acca[k], A0, k01.x); ffma2(accb[k], B0, k01.x);
                ffma2(acca[k], A1, k01.y); ffma2(accb[k], B1, k01.y);
                ffma2(acca[k], A2, k23.x); ffma2(accb[k], B2, k23.x);
                ffma2(acca[k], A3, k23.y); ffma2(accb[k], B3, k23.y);
            }
        }

        float s0, s1, s2, s3;
        unpack2(ssa, s0, s1);
        unpack2(ssb, s2, s3);
        float l0[KCLS], l1[KCLS], l2[KCLS], l3[KCLS];
#pragma unroll
        for (int k = 0; k < KCLS; k++) {
            unpack2(acca[k], l0[k], l1[k]);
            unpack2(accb[k], l2[k], l3[k]);
        }
        lsum += pix_loss(l0, s0, m.x);
        lsum += pix_loss(l1, s1, m.y);
        lsum += pix_loss(l2, s2, m.z);
        lsum += pix_loss(l3, s3, m.w);
    }

    // block reduction -> double atomic
#pragma unroll
    for (int o = 16; o; o >>= 1) lsum += __shfl_xor_sync(0xffffffffu, lsum, o);
    __shared__ float wsum[8];
    if ((threadIdx.x & 31) == 0) wsum[threadIdx.x >> 5] = lsum;
    __syncthreads();
    if (threadIdx.x < 8) {
        float v = wsum[threadIdx.x];
#pragma unroll
        for (int o = 4; o; o >>= 1) v += __shfl_xor_sync(0x000000ffu, v, o);
        if (threadIdx.x == 0) atomicAdd(&g_loss, (double)v);
    }
}

// -------- kernel 4: finalize --------
__global__ void k_fin(float* out) {
    const int np = g_numpos;
    out[0] = (float)(g_loss / (double)(np > 0 ? np : 1));
}

extern "C" void kernel_launch(void* const* d_in, const int* in_sizes, int n_in,
                              void* d_out, int out_size) {
    const float* feat = (const float*)d_in[0];
    const int*   gt   = (const int*)d_in[1];
    float*       out  = (float*)d_out;

    k_zero <<<5, 256>>>();
    k_proto<<<592, 256>>>(feat, gt);
    k_norm <<<1, KCLS * 32>>>();
    k_loss <<<592, 256>>>(feat);
    k_fin  <<<1, 1>>>(out);
}